// round 6
// baseline (speedup 1.0000x reference)
#include <cuda_runtime.h>

#define S 128
#define H 64
#define GRIDR 64
#define RPB 4                 // rays per block iteration
#define POOL (RPB * S)        // 512 candidate samples

__device__ int g_group_ctr;
__global__ void reset_ctr_kernel() { g_group_ctr = 0; }

// ---- packed f32x2 helpers (sm_100+ PTX; ptxas never auto-emits FFMA2) ----
__device__ __forceinline__ unsigned long long pack2(float v) {
    unsigned long long r;
    unsigned int u = __float_as_uint(v);
    asm("mov.b64 %0, {%1,%2};" : "=l"(r) : "r"(u), "r"(u));
    return r;
}
__device__ __forceinline__ void unpack2(unsigned long long v, float& lo, float& hi) {
    unsigned int a, b;
    asm("mov.b64 {%0,%1}, %2;" : "=r"(a), "=r"(b) : "l"(v));
    lo = __uint_as_float(a);
    hi = __uint_as_float(b);
}
__device__ __forceinline__ unsigned long long fma2(unsigned long long a,
                                                   unsigned long long b,
                                                   unsigned long long c) {
    unsigned long long d;
    asm("fma.rn.f32x2 %0, %1, %2, %3;" : "=l"(d) : "l"(a), "l"(b), "l"(c));
    return d;
}

__global__ void __launch_bounds__(128, 3) render_kernel(
    const float* __restrict__ rays_o, const float* __restrict__ rays_d,
    const float* __restrict__ near_, const float* __restrict__ far_,
    const float* __restrict__ jitter, const float* __restrict__ density,
    const float* __restrict__ W1, const float* __restrict__ b1,
    const float* __restrict__ W2, const float* __restrict__ b2,
    const float* __restrict__ Wsig, const float* __restrict__ bsig,
    const float* __restrict__ Wrgb, const float* __restrict__ brgb,
    float* __restrict__ out, int nrays)
{
    __shared__ __align__(16) float sW2[H * H];     // 16 KB, row k: 64 j-contiguous
    __shared__ __align__(16) float sb2[H];
    __shared__ __align__(16) float4 sW1p[H];       // {W1[0][k],W1[1][k],W1[2][k],b1[k]}
    __shared__ float sWsig[H];
    __shared__ float sWrgb[H * 3];
    __shared__ float sbias4[4];                    // bsig, brgb[0..2]
    __shared__ float s_px[POOL], s_py[POOL], s_pz[POOL];
    __shared__ int   s_orig[POOL];
    __shared__ float s_alpha[POOL], s_r[POOL], s_g[POOL], s_b[POOL];
    __shared__ float s_step[RPB];
    __shared__ int   s_cnt;
    __shared__ int   s_grp;

    const int tid = threadIdx.x;

    // ---- stage weights to shared ----
    for (int i = tid; i < H; i += 128) {
        sW1p[i] = make_float4(W1[i], W1[H + i], W1[2 * H + i], b1[i]);
        sb2[i] = b2[i];
        sWsig[i] = Wsig[i];
    }
    for (int i = tid; i < H * H; i += 128) sW2[i] = W2[i];
    for (int i = tid; i < H * 3; i += 128) sWrgb[i] = Wrgb[i];
    if (tid == 0) {
        sbias4[0] = bsig[0]; sbias4[1] = brgb[0];
        sbias4[2] = brgb[1]; sbias4[3] = brgb[2];
    }

    const int ngroups = (nrays + RPB - 1) / RPB;

    for (;;) {
        // ---- dynamic work fetch + per-group init ----
        if (tid == 0) {
            s_grp = atomicAdd(&g_group_ctr, 1);
            s_cnt = 0;
        }
        #pragma unroll
        for (int q = 0; q < RPB; q++) {
            const int i = q * S + tid;
            s_alpha[i] = 0.0f; s_r[i] = 0.0f; s_g[i] = 0.0f; s_b[i] = 0.0f;
        }
        __syncthreads();
        const int grp = s_grp;
        if (grp >= ngroups) break;
        const int ray0 = grp * RPB;

        // ---- phase A: occupancy test + compaction over RPB rays ----
        #pragma unroll
        for (int q = 0; q < RPB; q++) {
            const int ray = ray0 + q;
            if (ray >= nrays) break;
            const float ox = rays_o[ray * 3 + 0], oy = rays_o[ray * 3 + 1], oz = rays_o[ray * 3 + 2];
            const float dx = rays_d[ray * 3 + 0], dy = rays_d[ray * 3 + 1], dz = rays_d[ray * 3 + 2];
            const float nr = near_[ray], fr = far_[ray];
            const float step = (fr - nr) * (1.0f / (float)S);
            if (tid == 0) s_step[q] = step;

            const float z = nr + (float)tid * step;
            const float px0 = ox + z * dx;
            const float py0 = oy + z * dy;
            const float pz0 = oz + z * dz;
            // AABB min=(-1.25,-1.55,-1.25), extent 2.5 isotropic
            const float fx = ((px0 + 1.25f) * 0.4f) * 64.0f;
            const float fy = ((py0 + 1.55f) * 0.4f) * 64.0f;
            const float fz = ((pz0 + 1.25f) * 0.4f) * 64.0f;
            const int ix = (int)floorf(fx);
            const int iy = (int)floorf(fy);
            const int iz = (int)floorf(fz);
            const bool inb = (ix >= 0) & (ix < GRIDR) & (iy >= 0) & (iy < GRIDR) &
                             (iz >= 0) & (iz < GRIDR);
            bool active = false;
            if (inb) active = __ldg(&density[(ix * GRIDR + iy) * GRIDR + iz]) > 0.5f;

            float zv = active ? z : 0.0f;
            zv += jitter[ray * S + tid] * step;

            if (active) {
                const int slot = atomicAdd(&s_cnt, 1);
                s_px[slot] = ox + zv * dx;
                s_py[slot] = oy + zv * dy;
                s_pz[slot] = oz + zv * dz;
                s_orig[slot] = q * S + tid;
            }
        }
        __syncthreads();

        // ---- phase B: MLP, 2 samples per thread, h on the fly ----
        const int nact = s_cnt;
        for (int base = 0; base < nact; base += 256) {
            const int sA = base + 2 * tid;
            if (sA < nact) {
                const int sB = sA + 1;
                const bool has2 = (sB < nact);
                const int iB = has2 ? sB : sA;

                const float pxA = s_px[sA], pyA = s_py[sA], pzA = s_pz[sA];
                const float pxB = s_px[iB], pyB = s_py[iB], pzB = s_pz[iB];

                float sigA = sbias4[0], crA = sbias4[1], cgA = sbias4[2], cbA = sbias4[3];
                float sigB = sigA, crB = crA, cgB = cgA, cbB = cbA;

                #pragma unroll 1
                for (int j0 = 0; j0 < H; j0 += 32) {
                    unsigned long long accA[16], accB[16];
                    const ulonglong2* bv = (const ulonglong2*)(&sb2[j0]);
                    #pragma unroll
                    for (int p = 0; p < 8; p++) {
                        ulonglong2 t = bv[p];
                        accA[2 * p] = t.x;     accA[2 * p + 1] = t.y;
                        accB[2 * p] = t.x;     accB[2 * p + 1] = t.y;
                    }
                    #pragma unroll
                    for (int k = 0; k < H; k++) {
                        const float4 w1r = sW1p[k];
                        const float hA = fmaxf(
                            fmaf(pxA, w1r.x, fmaf(pyA, w1r.y, fmaf(pzA, w1r.z, w1r.w))), 0.0f);
                        const float hB = fmaxf(
                            fmaf(pxB, w1r.x, fmaf(pyB, w1r.y, fmaf(pzB, w1r.z, w1r.w))), 0.0f);
                        const unsigned long long hpA = pack2(hA);
                        const unsigned long long hpB = pack2(hB);
                        const ulonglong2* wv = (const ulonglong2*)(&sW2[k * H + j0]);
                        #pragma unroll
                        for (int p = 0; p < 8; p++) {
                            ulonglong2 w = wv[p];
                            accA[2 * p]     = fma2(hpA, w.x, accA[2 * p]);
                            accA[2 * p + 1] = fma2(hpA, w.y, accA[2 * p + 1]);
                            accB[2 * p]     = fma2(hpB, w.x, accB[2 * p]);
                            accB[2 * p + 1] = fma2(hpB, w.y, accB[2 * p + 1]);
                        }
                    }
                    #pragma unroll
                    for (int p = 0; p < 16; p++) {
                        const int j = j0 + 2 * p;
                        const float ws0 = sWsig[j],        ws1 = sWsig[j + 1];
                        const float wr0 = sWrgb[3 * j + 0], wr1 = sWrgb[3 * j + 3];
                        const float wg0 = sWrgb[3 * j + 1], wg1 = sWrgb[3 * j + 4];
                        const float wb0 = sWrgb[3 * j + 2], wb1 = sWrgb[3 * j + 5];
                        float lo, hi;
                        unpack2(accA[p], lo, hi);
                        lo = fmaxf(lo, 0.0f); hi = fmaxf(hi, 0.0f);
                        sigA = fmaf(lo, ws0, sigA); sigA = fmaf(hi, ws1, sigA);
                        crA = fmaf(lo, wr0, crA);   crA = fmaf(hi, wr1, crA);
                        cgA = fmaf(lo, wg0, cgA);   cgA = fmaf(hi, wg1, cgA);
                        cbA = fmaf(lo, wb0, cbA);   cbA = fmaf(hi, wb1, cbA);
                        unpack2(accB[p], lo, hi);
                        lo = fmaxf(lo, 0.0f); hi = fmaxf(hi, 0.0f);
                        sigB = fmaf(lo, ws0, sigB); sigB = fmaf(hi, ws1, sigB);
                        crB = fmaf(lo, wr0, crB);   crB = fmaf(hi, wr1, crB);
                        cgB = fmaf(lo, wg0, cgB);   cgB = fmaf(hi, wg1, cgB);
                        cbB = fmaf(lo, wb0, cbB);   cbB = fmaf(hi, wb1, cbB);
                    }
                }

                {
                    const int o = s_orig[sA];
                    const float step = s_step[o >> 7];
                    const float tau = fmaxf(sigA, 0.0f) * step;
                    s_alpha[o] = 1.0f - __expf(-tau);
                    s_r[o] = __fdividef(1.0f, 1.0f + __expf(-crA));
                    s_g[o] = __fdividef(1.0f, 1.0f + __expf(-cgA));
                    s_b[o] = __fdividef(1.0f, 1.0f + __expf(-cbA));
                }
                if (has2) {
                    const int o = s_orig[sB];
                    const float step = s_step[o >> 7];
                    const float tau = fmaxf(sigB, 0.0f) * step;
                    s_alpha[o] = 1.0f - __expf(-tau);
                    s_r[o] = __fdividef(1.0f, 1.0f + __expf(-crB));
                    s_g[o] = __fdividef(1.0f, 1.0f + __expf(-cgB));
                    s_b[o] = __fdividef(1.0f, 1.0f + __expf(-cbB));
                }
            }
        }
        __syncthreads();

        // ---- phase C: warp-scan composite, one warp per ray ----
        {
            const int w = tid >> 5;
            const int lane = tid & 31;
            const int ray = ray0 + w;
            if (ray < nrays) {
                const int rb = w * S;
                float ta[4];
                float pl = 1.0f;
                #pragma unroll
                for (int q = 0; q < 4; q++) {
                    const float a = s_alpha[rb + lane * 4 + q];
                    ta[q] = 1.0f - a + 1e-10f;
                    pl *= ta[q];
                }
                float inc = pl;
                #pragma unroll
                for (int off = 1; off < 32; off <<= 1) {
                    const float v = __shfl_up_sync(0xffffffffu, inc, off);
                    if (lane >= off) inc *= v;
                }
                const float total = __shfl_sync(0xffffffffu, inc, 31);
                float pre = __shfl_up_sync(0xffffffffu, inc, 1);
                if (lane == 0) pre = 1.0f;

                float T = pre, acr = 0.0f, acg = 0.0f, acb = 0.0f;
                #pragma unroll
                for (int q = 0; q < 4; q++) {
                    const int i = rb + lane * 4 + q;
                    const float a = s_alpha[i];
                    const float wgt = a * T;
                    acr = fmaf(wgt, s_r[i], acr);
                    acg = fmaf(wgt, s_g[i], acg);
                    acb = fmaf(wgt, s_b[i], acb);
                    T *= ta[q];
                }
                #pragma unroll
                for (int off = 16; off >= 1; off >>= 1) {
                    acr += __shfl_xor_sync(0xffffffffu, acr, off);
                    acg += __shfl_xor_sync(0xffffffffu, acg, off);
                    acb += __shfl_xor_sync(0xffffffffu, acb, off);
                }
                if (lane == 0) {
                    out[ray * 3 + 0] = acr + total;   // white background: + no_hit
                    out[ray * 3 + 1] = acg + total;
                    out[ray * 3 + 2] = acb + total;
                }
            }
        }
        __syncthreads();
    }
}

extern "C" void kernel_launch(void* const* d_in, const int* in_sizes, int n_in,
                              void* d_out, int out_size) {
    const float* rays_o  = (const float*)d_in[0];
    const float* rays_d  = (const float*)d_in[1];
    const float* near_   = (const float*)d_in[2];
    const float* far_    = (const float*)d_in[3];
    const float* jitter  = (const float*)d_in[4];
    const float* density = (const float*)d_in[5];
    const float* W1      = (const float*)d_in[6];
    const float* b1      = (const float*)d_in[7];
    const float* W2      = (const float*)d_in[8];
    const float* b2      = (const float*)d_in[9];
    const float* Wsig    = (const float*)d_in[10];
    const float* bsig    = (const float*)d_in[11];
    const float* Wrgb    = (const float*)d_in[12];
    const float* brgb    = (const float*)d_in[13];
    float* out = (float*)d_out;

    const int nrays = in_sizes[2];   // near has N elements

    reset_ctr_kernel<<<1, 1>>>();

    const int ngroups = (nrays + RPB - 1) / RPB;
    int grid = ngroups < 444 ? ngroups : 444;
    render_kernel<<<grid, 128>>>(rays_o, rays_d, near_, far_, jitter, density,
                                 W1, b1, W2, b2, Wsig, bsig, Wrgb, brgb,
                                 out, nrays);
}

// round 7
// speedup vs baseline: 1.0166x; 1.0166x over previous
#include <cuda_runtime.h>

#define S 128
#define H 64
#define GRIDR 64
#define RPB 8                 // rays per block iteration
#define POOL (RPB * S)        // 1024 candidate samples

__device__ int g_group_ctr;
__global__ void reset_ctr_kernel() { g_group_ctr = 0; }

// ---- packed f32x2 helpers (sm_100+ PTX; ptxas never auto-emits FFMA2) ----
__device__ __forceinline__ unsigned long long pack2(float v) {
    unsigned long long r;
    unsigned int u = __float_as_uint(v);
    asm("mov.b64 %0, {%1,%2};" : "=l"(r) : "r"(u), "r"(u));
    return r;
}
__device__ __forceinline__ void unpack2(unsigned long long v, float& lo, float& hi) {
    unsigned int a, b;
    asm("mov.b64 {%0,%1}, %2;" : "=r"(a), "=r"(b) : "l"(v));
    lo = __uint_as_float(a);
    hi = __uint_as_float(b);
}
__device__ __forceinline__ unsigned long long fma2(unsigned long long a,
                                                   unsigned long long b,
                                                   unsigned long long c) {
    unsigned long long d;
    asm("fma.rn.f32x2 %0, %1, %2, %3;" : "=l"(d) : "l"(a), "l"(b), "l"(c));
    return d;
}

__global__ void __launch_bounds__(128, 3) render_kernel(
    const float* __restrict__ rays_o, const float* __restrict__ rays_d,
    const float* __restrict__ near_, const float* __restrict__ far_,
    const float* __restrict__ jitter, const float* __restrict__ density,
    const float* __restrict__ W1, const float* __restrict__ b1,
    const float* __restrict__ W2, const float* __restrict__ b2,
    const float* __restrict__ Wsig, const float* __restrict__ bsig,
    const float* __restrict__ Wrgb, const float* __restrict__ brgb,
    float* __restrict__ out, int nrays)
{
    __shared__ __align__(16) float sW2[H * H];     // 16 KB, row k: 64 j-contiguous
    __shared__ __align__(16) float sb2[H];
    __shared__ __align__(16) float4 sW1p[H];       // {W1[0][k],W1[1][k],W1[2][k],b1[k]}
    __shared__ float sWsig[H];
    __shared__ float sWrgb[H * 3];
    __shared__ float sbias4[4];                    // bsig, brgb[0..2]
    __shared__ float s_px[POOL], s_py[POOL], s_pz[POOL];
    __shared__ int   s_orig[POOL];
    __shared__ float s_alpha[POOL], s_r[POOL], s_g[POOL], s_b[POOL];
    __shared__ float s_step[RPB];
    __shared__ int   s_cnt;
    __shared__ int   s_grp;

    const int tid = threadIdx.x;

    // ---- stage weights to shared ----
    for (int i = tid; i < H; i += 128) {
        sW1p[i] = make_float4(W1[i], W1[H + i], W1[2 * H + i], b1[i]);
        sb2[i] = b2[i];
        sWsig[i] = Wsig[i];
    }
    for (int i = tid; i < H * H; i += 128) sW2[i] = W2[i];
    for (int i = tid; i < H * 3; i += 128) sWrgb[i] = Wrgb[i];
    if (tid == 0) {
        sbias4[0] = bsig[0]; sbias4[1] = brgb[0];
        sbias4[2] = brgb[1]; sbias4[3] = brgb[2];
    }

    const int ngroups = (nrays + RPB - 1) / RPB;

    for (;;) {
        // ---- dynamic work fetch + per-group init ----
        if (tid == 0) {
            s_grp = atomicAdd(&g_group_ctr, 1);
            s_cnt = 0;
        }
        #pragma unroll
        for (int q = 0; q < RPB; q++) {
            const int i = q * S + tid;
            s_alpha[i] = 0.0f; s_r[i] = 0.0f; s_g[i] = 0.0f; s_b[i] = 0.0f;
        }
        __syncthreads();
        const int grp = s_grp;
        if (grp >= ngroups) break;
        const int ray0 = grp * RPB;

        // ---- phase A: occupancy test + compaction over RPB rays ----
        #pragma unroll
        for (int q = 0; q < RPB; q++) {
            const int ray = ray0 + q;
            if (ray >= nrays) break;
            const float ox = rays_o[ray * 3 + 0], oy = rays_o[ray * 3 + 1], oz = rays_o[ray * 3 + 2];
            const float dx = rays_d[ray * 3 + 0], dy = rays_d[ray * 3 + 1], dz = rays_d[ray * 3 + 2];
            const float nr = near_[ray], fr = far_[ray];
            const float step = (fr - nr) * (1.0f / (float)S);
            if (tid == 0) s_step[q] = step;

            const float z = nr + (float)tid * step;
            const float px0 = ox + z * dx;
            const float py0 = oy + z * dy;
            const float pz0 = oz + z * dz;
            // AABB min=(-1.25,-1.55,-1.25), extent 2.5 isotropic
            const float fx = ((px0 + 1.25f) * 0.4f) * 64.0f;
            const float fy = ((py0 + 1.55f) * 0.4f) * 64.0f;
            const float fz = ((pz0 + 1.25f) * 0.4f) * 64.0f;
            const int ix = (int)floorf(fx);
            const int iy = (int)floorf(fy);
            const int iz = (int)floorf(fz);
            const bool inb = (ix >= 0) & (ix < GRIDR) & (iy >= 0) & (iy < GRIDR) &
                             (iz >= 0) & (iz < GRIDR);
            bool active = false;
            if (inb) active = __ldg(&density[(ix * GRIDR + iy) * GRIDR + iz]) > 0.5f;

            float zv = active ? z : 0.0f;
            zv += jitter[ray * S + tid] * step;

            if (active) {
                const int slot = atomicAdd(&s_cnt, 1);
                s_px[slot] = ox + zv * dx;
                s_py[slot] = oy + zv * dy;
                s_pz[slot] = oz + zv * dz;
                s_orig[slot] = q * S + tid;
            }
        }
        __syncthreads();

        // ---- phase B: MLP, 2 samples per thread, h on the fly ----
        const int nact = s_cnt;
        for (int base = 0; base < nact; base += 256) {
            const int sA = base + 2 * tid;
            if (sA < nact) {
                const int sB = sA + 1;
                const bool has2 = (sB < nact);
                const int iB = has2 ? sB : sA;

                const float pxA = s_px[sA], pyA = s_py[sA], pzA = s_pz[sA];
                const float pxB = s_px[iB], pyB = s_py[iB], pzB = s_pz[iB];

                float sigA = sbias4[0], crA = sbias4[1], cgA = sbias4[2], cbA = sbias4[3];
                float sigB = sigA, crB = crA, cgB = cgA, cbB = cbA;

                #pragma unroll 1
                for (int j0 = 0; j0 < H; j0 += 32) {
                    unsigned long long accA[16], accB[16];
                    const ulonglong2* bv = (const ulonglong2*)(&sb2[j0]);
                    #pragma unroll
                    for (int p = 0; p < 8; p++) {
                        ulonglong2 t = bv[p];
                        accA[2 * p] = t.x;     accA[2 * p + 1] = t.y;
                        accB[2 * p] = t.x;     accB[2 * p + 1] = t.y;
                    }
                    #pragma unroll
                    for (int k = 0; k < H; k++) {
                        const float4 w1r = sW1p[k];
                        const float hA = fmaxf(
                            fmaf(pxA, w1r.x, fmaf(pyA, w1r.y, fmaf(pzA, w1r.z, w1r.w))), 0.0f);
                        const float hB = fmaxf(
                            fmaf(pxB, w1r.x, fmaf(pyB, w1r.y, fmaf(pzB, w1r.z, w1r.w))), 0.0f);
                        const unsigned long long hpA = pack2(hA);
                        const unsigned long long hpB = pack2(hB);
                        const ulonglong2* wv = (const ulonglong2*)(&sW2[k * H + j0]);
                        #pragma unroll
                        for (int p = 0; p < 8; p++) {
                            ulonglong2 w = wv[p];
                            accA[2 * p]     = fma2(hpA, w.x, accA[2 * p]);
                            accA[2 * p + 1] = fma2(hpA, w.y, accA[2 * p + 1]);
                            accB[2 * p]     = fma2(hpB, w.x, accB[2 * p]);
                            accB[2 * p + 1] = fma2(hpB, w.y, accB[2 * p + 1]);
                        }
                    }
                    #pragma unroll
                    for (int p = 0; p < 16; p++) {
                        const int j = j0 + 2 * p;
                        const float ws0 = sWsig[j],        ws1 = sWsig[j + 1];
                        const float wr0 = sWrgb[3 * j + 0], wr1 = sWrgb[3 * j + 3];
                        const float wg0 = sWrgb[3 * j + 1], wg1 = sWrgb[3 * j + 4];
                        const float wb0 = sWrgb[3 * j + 2], wb1 = sWrgb[3 * j + 5];
                        float lo, hi;
                        unpack2(accA[p], lo, hi);
                        lo = fmaxf(lo, 0.0f); hi = fmaxf(hi, 0.0f);
                        sigA = fmaf(lo, ws0, sigA); sigA = fmaf(hi, ws1, sigA);
                        crA = fmaf(lo, wr0, crA);   crA = fmaf(hi, wr1, crA);
                        cgA = fmaf(lo, wg0, cgA);   cgA = fmaf(hi, wg1, cgA);
                        cbA = fmaf(lo, wb0, cbA);   cbA = fmaf(hi, wb1, cbA);
                        unpack2(accB[p], lo, hi);
                        lo = fmaxf(lo, 0.0f); hi = fmaxf(hi, 0.0f);
                        sigB = fmaf(lo, ws0, sigB); sigB = fmaf(hi, ws1, sigB);
                        crB = fmaf(lo, wr0, crB);   crB = fmaf(hi, wr1, crB);
                        cgB = fmaf(lo, wg0, cgB);   cgB = fmaf(hi, wg1, cgB);
                        cbB = fmaf(lo, wb0, cbB);   cbB = fmaf(hi, wb1, cbB);
                    }
                }

                {
                    const int o = s_orig[sA];
                    const float step = s_step[o >> 7];
                    const float tau = fmaxf(sigA, 0.0f) * step;
                    s_alpha[o] = 1.0f - __expf(-tau);
                    s_r[o] = __fdividef(1.0f, 1.0f + __expf(-crA));
                    s_g[o] = __fdividef(1.0f, 1.0f + __expf(-cgA));
                    s_b[o] = __fdividef(1.0f, 1.0f + __expf(-cbA));
                }
                if (has2) {
                    const int o = s_orig[sB];
                    const float step = s_step[o >> 7];
                    const float tau = fmaxf(sigB, 0.0f) * step;
                    s_alpha[o] = 1.0f - __expf(-tau);
                    s_r[o] = __fdividef(1.0f, 1.0f + __expf(-crB));
                    s_g[o] = __fdividef(1.0f, 1.0f + __expf(-cgB));
                    s_b[o] = __fdividef(1.0f, 1.0f + __expf(-cbB));
                }
            }
        }
        __syncthreads();

        // ---- phase C: warp-scan composite, 4 warps cover RPB rays ----
        {
            const int lane = tid & 31;
            for (int w = (tid >> 5); w < RPB; w += 4) {
                const int ray = ray0 + w;
                if (ray >= nrays) continue;
                const int rb = w * S;
                float ta[4];
                float pl = 1.0f;
                #pragma unroll
                for (int q = 0; q < 4; q++) {
                    const float a = s_alpha[rb + lane * 4 + q];
                    ta[q] = 1.0f - a + 1e-10f;
                    pl *= ta[q];
                }
                float inc = pl;
                #pragma unroll
                for (int off = 1; off < 32; off <<= 1) {
                    const float v = __shfl_up_sync(0xffffffffu, inc, off);
                    if (lane >= off) inc *= v;
                }
                const float total = __shfl_sync(0xffffffffu, inc, 31);
                float pre = __shfl_up_sync(0xffffffffu, inc, 1);
                if (lane == 0) pre = 1.0f;

                float T = pre, acr = 0.0f, acg = 0.0f, acb = 0.0f;
                #pragma unroll
                for (int q = 0; q < 4; q++) {
                    const int i = rb + lane * 4 + q;
                    const float a = s_alpha[i];
                    const float wgt = a * T;
                    acr = fmaf(wgt, s_r[i], acr);
                    acg = fmaf(wgt, s_g[i], acg);
                    acb = fmaf(wgt, s_b[i], acb);
                    T *= ta[q];
                }
                #pragma unroll
                for (int off = 16; off >= 1; off >>= 1) {
                    acr += __shfl_xor_sync(0xffffffffu, acr, off);
                    acg += __shfl_xor_sync(0xffffffffu, acg, off);
                    acb += __shfl_xor_sync(0xffffffffu, acb, off);
                }
                if (lane == 0) {
                    out[ray * 3 + 0] = acr + total;   // white background: + no_hit
                    out[ray * 3 + 1] = acg + total;
                    out[ray * 3 + 2] = acb + total;
                }
            }
        }
        __syncthreads();
    }
}

extern "C" void kernel_launch(void* const* d_in, const int* in_sizes, int n_in,
                              void* d_out, int out_size) {
    const float* rays_o  = (const float*)d_in[0];
    const float* rays_d  = (const float*)d_in[1];
    const float* near_   = (const float*)d_in[2];
    const float* far_    = (const float*)d_in[3];
    const float* jitter  = (const float*)d_in[4];
    const float* density = (const float*)d_in[5];
    const float* W1      = (const float*)d_in[6];
    const float* b1      = (const float*)d_in[7];
    const float* W2      = (const float*)d_in[8];
    const float* b2      = (const float*)d_in[9];
    const float* Wsig    = (const float*)d_in[10];
    const float* bsig    = (const float*)d_in[11];
    const float* Wrgb    = (const float*)d_in[12];
    const float* brgb    = (const float*)d_in[13];
    float* out = (float*)d_out;

    const int nrays = in_sizes[2];   // near has N elements

    reset_ctr_kernel<<<1, 1>>>();

    const int ngroups = (nrays + RPB - 1) / RPB;
    int grid = ngroups < 444 ? ngroups : 444;
    render_kernel<<<grid, 128>>>(rays_o, rays_d, near_, far_, jitter, density,
                                 W1, b1, W2, b2, Wsig, bsig, Wrgb, brgb,
                                 out, nrays);
}

// round 8
// speedup vs baseline: 1.3270x; 1.3053x over previous
#include <cuda_runtime.h>

#define S 128
#define H 64
#define GRIDR 64
#define NMAX 8192
#define MLP_GRID 444
#define MLP_BLK 128

__device__ int    g_cnt;
__device__ float4 g_pts[NMAX * S];    // (px,py,pz, id-as-float-bits)
__device__ float4 g_rgba[NMAX * S];   // (r,g,b,alpha)

__global__ void reset_ctr_kernel() { g_cnt = 0; }

// ---- packed f32x2 helpers ----
__device__ __forceinline__ unsigned long long pack2(float v) {
    unsigned long long r;
    unsigned int u = __float_as_uint(v);
    asm("mov.b64 %0, {%1,%2};" : "=l"(r) : "r"(u), "r"(u));
    return r;
}
__device__ __forceinline__ void unpack2(unsigned long long v, float& lo, float& hi) {
    unsigned int a, b;
    asm("mov.b64 {%0,%1}, %2;" : "=r"(a), "=r"(b) : "l"(v));
    lo = __uint_as_float(a);
    hi = __uint_as_float(b);
}
__device__ __forceinline__ unsigned long long fma2(unsigned long long a,
                                                   unsigned long long b,
                                                   unsigned long long c) {
    unsigned long long d;
    asm("fma.rn.f32x2 %0, %1, %2, %3;" : "=l"(d) : "l"(a), "l"(b), "l"(c));
    return d;
}

// ================= kernel 1: occupancy test + global compaction =================
// block = 256 threads = 2 rays x 128 samples
__global__ void __launch_bounds__(256) compact_kernel(
    const float* __restrict__ rays_o, const float* __restrict__ rays_d,
    const float* __restrict__ near_, const float* __restrict__ far_,
    const float* __restrict__ jitter, const float* __restrict__ density,
    int nrays)
{
    __shared__ int warp_base[8];

    const int tid = threadIdx.x;
    const int q   = tid >> 7;          // 0..1 ray-in-block
    const int s   = tid & 127;         // sample index
    const int ray = blockIdx.x * 2 + q;
    const int wid = tid >> 5;
    const int lane = tid & 31;

    bool active = false;
    float px = 0.f, py = 0.f, pz = 0.f;
    int id = 0;

    if (ray < nrays) {
        const float ox = rays_o[ray * 3 + 0], oy = rays_o[ray * 3 + 1], oz = rays_o[ray * 3 + 2];
        const float dx = rays_d[ray * 3 + 0], dy = rays_d[ray * 3 + 1], dz = rays_d[ray * 3 + 2];
        const float nr = near_[ray], fr = far_[ray];
        const float step = (fr - nr) * (1.0f / (float)S);

        const float z = nr + (float)s * step;
        const float px0 = ox + z * dx;
        const float py0 = oy + z * dy;
        const float pz0 = oz + z * dz;
        // AABB min=(-1.25,-1.55,-1.25), extent 2.5 isotropic
        const float fx = ((px0 + 1.25f) * 0.4f) * 64.0f;
        const float fy = ((py0 + 1.55f) * 0.4f) * 64.0f;
        const float fz = ((pz0 + 1.25f) * 0.4f) * 64.0f;
        const int ix = (int)floorf(fx);
        const int iy = (int)floorf(fy);
        const int iz = (int)floorf(fz);
        const bool inb = (ix >= 0) & (ix < GRIDR) & (iy >= 0) & (iy < GRIDR) &
                         (iz >= 0) & (iz < GRIDR);
        if (inb) active = __ldg(&density[(ix * GRIDR + iy) * GRIDR + iz]) > 0.5f;

        float zv = active ? z : 0.0f;
        zv += jitter[ray * S + s] * step;

        px = ox + zv * dx;
        py = oy + zv * dy;
        pz = oz + zv * dz;
        id = (ray << 7) | s;

        // zero the result slot (inactive samples contribute alpha=0, rgb=0)
        g_rgba[id] = make_float4(0.f, 0.f, 0.f, 0.f);
    }

    // ---- block-wide compaction ----
    const unsigned ballot = __ballot_sync(0xffffffffu, active);
    if (lane == 0) warp_base[wid] = __popc(ballot);
    __syncthreads();
    if (tid == 0) {
        int sum = 0;
        #pragma unroll
        for (int w = 0; w < 8; w++) { int c = warp_base[w]; warp_base[w] = sum; sum += c; }
        const int base = atomicAdd(&g_cnt, sum);
        #pragma unroll
        for (int w = 0; w < 8; w++) warp_base[w] += base;
    }
    __syncthreads();
    if (active) {
        const int idx = warp_base[wid] + __popc(ballot & ((1u << lane) - 1u));
        g_pts[idx] = make_float4(px, py, pz, __int_as_float(id));
    }
}

// ================= kernel 2: MLP over compacted samples =================
__global__ void __launch_bounds__(MLP_BLK, 3) mlp_kernel(
    const float* __restrict__ near_, const float* __restrict__ far_,
    const float* __restrict__ W1, const float* __restrict__ b1,
    const float* __restrict__ W2, const float* __restrict__ b2,
    const float* __restrict__ Wsig, const float* __restrict__ bsig,
    const float* __restrict__ Wrgb, const float* __restrict__ brgb)
{
    __shared__ __align__(16) float sW2[H * H];     // 16 KB
    __shared__ __align__(16) float sb2[H];
    __shared__ __align__(16) float4 sW1p[H];       // {W1[0][k],W1[1][k],W1[2][k],b1[k]}
    __shared__ float sWsig[H];
    __shared__ float sWrgb[H * 3];
    __shared__ float sbias4[4];

    const int tid = threadIdx.x;

    for (int i = tid; i < H; i += MLP_BLK) {
        sW1p[i] = make_float4(W1[i], W1[H + i], W1[2 * H + i], b1[i]);
        sb2[i] = b2[i];
        sWsig[i] = Wsig[i];
    }
    for (int i = tid; i < H * H; i += MLP_BLK) sW2[i] = W2[i];
    for (int i = tid; i < H * 3; i += MLP_BLK) sWrgb[i] = Wrgb[i];
    if (tid == 0) {
        sbias4[0] = bsig[0]; sbias4[1] = brgb[0];
        sbias4[2] = brgb[1]; sbias4[3] = brgb[2];
    }
    __syncthreads();

    const int cnt = g_cnt;
    const int stride = gridDim.x * MLP_BLK;

    for (int i = blockIdx.x * MLP_BLK + tid; i < cnt; i += stride) {
        const float4 pt = g_pts[i];
        const float px = pt.x, py = pt.y, pz = pt.z;
        const int id = __float_as_int(pt.w);

        float h1[H];
        #pragma unroll
        for (int k = 0; k < H; k++) {
            const float4 w1r = sW1p[k];
            h1[k] = fmaxf(
                fmaf(px, w1r.x, fmaf(py, w1r.y, fmaf(pz, w1r.z, w1r.w))), 0.0f);
        }

        float sig = sbias4[0], cr = sbias4[1], cg = sbias4[2], cb = sbias4[3];

        #pragma unroll 1
        for (int j0 = 0; j0 < H; j0 += 32) {
            unsigned long long acc[16];
            const ulonglong2* bv = (const ulonglong2*)(&sb2[j0]);
            #pragma unroll
            for (int p = 0; p < 8; p++) {
                ulonglong2 t = bv[p];
                acc[2 * p] = t.x;
                acc[2 * p + 1] = t.y;
            }
            #pragma unroll
            for (int k = 0; k < H; k++) {
                const unsigned long long hp = pack2(h1[k]);
                const ulonglong2* wv = (const ulonglong2*)(&sW2[k * H + j0]);
                #pragma unroll
                for (int p = 0; p < 8; p++) {
                    ulonglong2 w = wv[p];
                    acc[2 * p]     = fma2(hp, w.x, acc[2 * p]);
                    acc[2 * p + 1] = fma2(hp, w.y, acc[2 * p + 1]);
                }
            }
            #pragma unroll
            for (int p = 0; p < 16; p++) {
                float lo, hi;
                unpack2(acc[p], lo, hi);
                lo = fmaxf(lo, 0.0f);
                hi = fmaxf(hi, 0.0f);
                const int j = j0 + 2 * p;
                sig = fmaf(lo, sWsig[j], sig);
                sig = fmaf(hi, sWsig[j + 1], sig);
                cr = fmaf(lo, sWrgb[3 * j + 0], cr);
                cr = fmaf(hi, sWrgb[3 * j + 3], cr);
                cg = fmaf(lo, sWrgb[3 * j + 1], cg);
                cg = fmaf(hi, sWrgb[3 * j + 4], cg);
                cb = fmaf(lo, sWrgb[3 * j + 2], cb);
                cb = fmaf(hi, sWrgb[3 * j + 5], cb);
            }
        }

        const int ray = id >> 7;
        const float step = (__ldg(&far_[ray]) - __ldg(&near_[ray])) * (1.0f / (float)S);
        const float tau = fmaxf(sig, 0.0f) * step;
        const float alpha = 1.0f - __expf(-tau);
        const float r = __fdividef(1.0f, 1.0f + __expf(-cr));
        const float g = __fdividef(1.0f, 1.0f + __expf(-cg));
        const float b = __fdividef(1.0f, 1.0f + __expf(-cb));

        g_rgba[id] = make_float4(r, g, b, alpha);
    }
}

// ================= kernel 3: per-ray alpha composite =================
// block = 256 threads = 8 warps = 8 rays
__global__ void __launch_bounds__(256) composite_kernel(
    float* __restrict__ out, int nrays)
{
    const int tid = threadIdx.x;
    const int wid = tid >> 5;
    const int lane = tid & 31;
    const int ray = blockIdx.x * 8 + wid;
    if (ray >= nrays) return;

    const float4* rp = &g_rgba[ray << 7];

    float4 v[4];
    float ta[4];
    float pl = 1.0f;
    #pragma unroll
    for (int q = 0; q < 4; q++) {
        v[q] = rp[lane * 4 + q];
        ta[q] = 1.0f - v[q].w + 1e-10f;
        pl *= ta[q];
    }
    // inclusive product scan across lanes
    float inc = pl;
    #pragma unroll
    for (int off = 1; off < 32; off <<= 1) {
        const float t = __shfl_up_sync(0xffffffffu, inc, off);
        if (lane >= off) inc *= t;
    }
    const float total = __shfl_sync(0xffffffffu, inc, 31);
    float pre = __shfl_up_sync(0xffffffffu, inc, 1);
    if (lane == 0) pre = 1.0f;

    float T = pre, acr = 0.0f, acg = 0.0f, acb = 0.0f;
    #pragma unroll
    for (int q = 0; q < 4; q++) {
        const float w = v[q].w * T;
        acr = fmaf(w, v[q].x, acr);
        acg = fmaf(w, v[q].y, acg);
        acb = fmaf(w, v[q].z, acb);
        T *= ta[q];
    }
    #pragma unroll
    for (int off = 16; off >= 1; off >>= 1) {
        acr += __shfl_xor_sync(0xffffffffu, acr, off);
        acg += __shfl_xor_sync(0xffffffffu, acg, off);
        acb += __shfl_xor_sync(0xffffffffu, acb, off);
    }
    if (lane == 0) {
        out[ray * 3 + 0] = acr + total;   // white background: + no_hit
        out[ray * 3 + 1] = acg + total;
        out[ray * 3 + 2] = acb + total;
    }
}

extern "C" void kernel_launch(void* const* d_in, const int* in_sizes, int n_in,
                              void* d_out, int out_size) {
    const float* rays_o  = (const float*)d_in[0];
    const float* rays_d  = (const float*)d_in[1];
    const float* near_   = (const float*)d_in[2];
    const float* far_    = (const float*)d_in[3];
    const float* jitter  = (const float*)d_in[4];
    const float* density = (const float*)d_in[5];
    const float* W1      = (const float*)d_in[6];
    const float* b1      = (const float*)d_in[7];
    const float* W2      = (const float*)d_in[8];
    const float* b2      = (const float*)d_in[9];
    const float* Wsig    = (const float*)d_in[10];
    const float* bsig    = (const float*)d_in[11];
    const float* Wrgb    = (const float*)d_in[12];
    const float* brgb    = (const float*)d_in[13];
    float* out = (float*)d_out;

    const int nrays = in_sizes[2];   // near has N elements

    reset_ctr_kernel<<<1, 1>>>();
    compact_kernel<<<(nrays + 1) / 2, 256>>>(rays_o, rays_d, near_, far_,
                                             jitter, density, nrays);
    mlp_kernel<<<MLP_GRID, MLP_BLK>>>(near_, far_, W1, b1, W2, b2,
                                      Wsig, bsig, Wrgb, brgb);
    composite_kernel<<<(nrays + 7) / 8, 256>>>(out, nrays);
}

// round 10
// speedup vs baseline: 2.5504x; 1.9219x over previous
#include <cuda_runtime.h>

#define S 128
#define H 64
#define GRIDR 64
#define NMAX 8192
#define MLP_GRID 444
#define MLP_BLK 128

__device__ int    g_cnt;
__device__ float4 g_pts[NMAX * S];    // (px,py,pz, id-as-float-bits)
__device__ float4 g_rgba[NMAX * S];   // (r,g,b,alpha)

__global__ void reset_ctr_kernel() { g_cnt = 0; }

// ---- f16 helpers ----
__device__ __forceinline__ float f16_round(float v) {
    unsigned short h;
    asm("cvt.rn.f16.f32 %0, %1;" : "=h"(h) : "f"(v));
    float r;
    asm("cvt.f32.f16 %0, %1;" : "=f"(r) : "h"(h));
    return r;
}
// pack two floats to f16x2: LOW half = first arg (lower index element)
__device__ __forceinline__ unsigned f16x2_of(float lo_v, float hi_v) {
    unsigned r;
    asm("cvt.rn.f16x2.f32 %0, %1, %2;" : "=r"(r) : "f"(hi_v), "f"(lo_v));
    return r;
}
__device__ __forceinline__ void mma16816(
    float& d0, float& d1, float& d2, float& d3,
    unsigned a0, unsigned a1, unsigned a2, unsigned a3,
    unsigned b0, unsigned b1,
    float c0, float c1, float c2, float c3)
{
    asm("mma.sync.aligned.m16n8k16.row.col.f32.f16.f16.f32 "
        "{%0,%1,%2,%3}, {%4,%5,%6,%7}, {%8,%9}, {%10,%11,%12,%13};"
        : "=f"(d0), "=f"(d1), "=f"(d2), "=f"(d3)
        : "r"(a0), "r"(a1), "r"(a2), "r"(a3), "r"(b0), "r"(b1),
          "f"(c0), "f"(c1), "f"(c2), "f"(c3));
}

// ================= kernel 1: occupancy test + global compaction =================
__global__ void __launch_bounds__(256) compact_kernel(
    const float* __restrict__ rays_o, const float* __restrict__ rays_d,
    const float* __restrict__ near_, const float* __restrict__ far_,
    const float* __restrict__ jitter, const float* __restrict__ density,
    int nrays)
{
    __shared__ int warp_base[8];

    const int tid = threadIdx.x;
    const int q   = tid >> 7;
    const int s   = tid & 127;
    const int ray = blockIdx.x * 2 + q;
    const int wid = tid >> 5;
    const int lane = tid & 31;

    bool active = false;
    float px = 0.f, py = 0.f, pz = 0.f;
    int id = 0;

    if (ray < nrays) {
        const float ox = rays_o[ray * 3 + 0], oy = rays_o[ray * 3 + 1], oz = rays_o[ray * 3 + 2];
        const float dx = rays_d[ray * 3 + 0], dy = rays_d[ray * 3 + 1], dz = rays_d[ray * 3 + 2];
        const float nr = near_[ray], fr = far_[ray];
        const float step = (fr - nr) * (1.0f / (float)S);

        const float z = nr + (float)s * step;
        const float px0 = ox + z * dx;
        const float py0 = oy + z * dy;
        const float pz0 = oz + z * dz;
        const float fx = ((px0 + 1.25f) * 0.4f) * 64.0f;
        const float fy = ((py0 + 1.55f) * 0.4f) * 64.0f;
        const float fz = ((pz0 + 1.25f) * 0.4f) * 64.0f;
        const int ix = (int)floorf(fx);
        const int iy = (int)floorf(fy);
        const int iz = (int)floorf(fz);
        const bool inb = (ix >= 0) & (ix < GRIDR) & (iy >= 0) & (iy < GRIDR) &
                         (iz >= 0) & (iz < GRIDR);
        if (inb) active = __ldg(&density[(ix * GRIDR + iy) * GRIDR + iz]) > 0.5f;

        float zv = active ? z : 0.0f;
        zv += jitter[ray * S + s] * step;

        px = ox + zv * dx;
        py = oy + zv * dy;
        pz = oz + zv * dz;
        id = (ray << 7) | s;

        g_rgba[id] = make_float4(0.f, 0.f, 0.f, 0.f);
    }

    const unsigned ballot = __ballot_sync(0xffffffffu, active);
    if (lane == 0) warp_base[wid] = __popc(ballot);
    __syncthreads();
    if (tid == 0) {
        int sum = 0;
        #pragma unroll
        for (int w = 0; w < 8; w++) { int c = warp_base[w]; warp_base[w] = sum; sum += c; }
        const int base = atomicAdd(&g_cnt, sum);
        #pragma unroll
        for (int w = 0; w < 8; w++) warp_base[w] += base;
    }
    __syncthreads();
    if (active) {
        const int idx = warp_base[wid] + __popc(ballot & ((1u << lane) - 1u));
        g_pts[idx] = make_float4(px, py, pz, __int_as_float(id));
    }
}

// ================= kernel 2: tensor-core MLP over compacted samples =================
// Per warp-iteration: 16 samples (M), chained m16n8k16 f16 mma, hi/lo 3-mma for accuracy.
__global__ void __launch_bounds__(MLP_BLK, 3) mlp_kernel(
    const float* __restrict__ near_, const float* __restrict__ far_,
    const float* __restrict__ W1, const float* __restrict__ b1,
    const float* __restrict__ W2, const float* __restrict__ b2,
    const float* __restrict__ Wsig, const float* __restrict__ bsig,
    const float* __restrict__ Wrgb, const float* __restrict__ brgb)
{
    // weight fragments, pre-packed: uint4 = {b0_hi, b1_hi, b0_lo, b1_lo}
    __shared__ __align__(16) uint4 sW1f[8][32];    // layer1: kt=0, nt=0..7
    __shared__ __align__(16) uint4 sW2f[32][32];   // layer2: [kt*8+nt]
    __shared__ __align__(16) uint4 sB3f[4][32];    // heads:  kt=0..3, nt=0
    __shared__ float s_b2[H];
    __shared__ float s_bias4[4];                   // bsig, brgb[0..2]

    const int tid = threadIdx.x;

    // ---- prepack weights into fragment order ----
    for (int e = tid; e < 44 * 32; e += MLP_BLK) {
        const int lane = e & 31, tile = e >> 5;
        const int q = lane & 3, gr = lane >> 2;
        float v[4];
        if (tile < 8) {                      // B1[16][64]: rows 0-2 = W1, row3 = b1, rest 0
            const int n = tile * 8 + gr;
            #pragma unroll
            for (int j = 0; j < 4; j++) {
                const int k = ((j >> 1) << 3) + 2 * q + (j & 1);
                v[j] = (k < 3) ? W1[k * H + n] : (k == 3 ? b1[n] : 0.0f);
            }
        } else if (tile < 40) {              // B2 = W2[64][64]
            const int t = tile - 8;
            const int kt = t >> 3, nt = t & 7;
            const int n = nt * 8 + gr;
            #pragma unroll
            for (int j = 0; j < 4; j++) {
                const int k = kt * 16 + ((j >> 1) << 3) + 2 * q + (j & 1);
                v[j] = W2[k * H + n];
            }
        } else {                             // B3[64][8]: col0 Wsig, cols1-3 Wrgb, rest 0
            const int kt = tile - 40;
            const int n = gr;
            #pragma unroll
            for (int j = 0; j < 4; j++) {
                const int k = kt * 16 + ((j >> 1) << 3) + 2 * q + (j & 1);
                v[j] = (n == 0) ? Wsig[k] : (n < 4 ? Wrgb[k * 3 + (n - 1)] : 0.0f);
            }
        }
        const float h0 = f16_round(v[0]), h1v = f16_round(v[1]);
        const float h2 = f16_round(v[2]), h3v = f16_round(v[3]);
        uint4 pk;
        pk.x = f16x2_of(h0, h1v);
        pk.y = f16x2_of(h2, h3v);
        pk.z = f16x2_of(v[0] - h0, v[1] - h1v);
        pk.w = f16x2_of(v[2] - h2, v[3] - h3v);
        if (tile < 8)       sW1f[tile][lane] = pk;
        else if (tile < 40) sW2f[tile - 8][lane] = pk;
        else                sB3f[tile - 40][lane] = pk;
    }
    for (int i = tid; i < H; i += MLP_BLK) s_b2[i] = b2[i];
    if (tid == 0) {
        s_bias4[0] = bsig[0]; s_bias4[1] = brgb[0];
        s_bias4[2] = brgb[1]; s_bias4[3] = brgb[2];
    }
    __syncthreads();

    const int cnt = g_cnt;
    const int warp = tid >> 5, lane = tid & 31;
    const int q = lane & 3, gr = lane >> 2;
    const float* P = (const float*)g_pts;
    const int stride = gridDim.x * 4 * 16;

    for (int base = (blockIdx.x * 4 + warp) * 16; base < cnt; base += stride) {
        const int i0 = min(base + gr, cnt - 1);
        const int i1 = min(base + gr + 8, cnt - 1);

        // ---- A1 fragment: P[16 samples][16] = (px,py,pz,1, 0...) ----
        unsigned a1h0 = 0, a1h1 = 0, a1l0 = 0, a1l1 = 0;
        if (q < 2) {
            float u0, v0, u1, v1;
            if (q == 0) {
                float2 t0 = *(const float2*)&P[i0 * 4];
                float2 t1 = *(const float2*)&P[i1 * 4];
                u0 = t0.x; v0 = t0.y; u1 = t1.x; v1 = t1.y;
            } else {
                u0 = P[i0 * 4 + 2]; v0 = 1.0f;
                u1 = P[i1 * 4 + 2]; v1 = 1.0f;
            }
            const float u0h = f16_round(u0), v0h = f16_round(v0);
            const float u1h = f16_round(u1), v1h = f16_round(v1);
            a1h0 = f16x2_of(u0h, v0h);  a1l0 = f16x2_of(u0 - u0h, v0 - v0h);
            a1h1 = f16x2_of(u1h, v1h);  a1l1 = f16x2_of(u1 - u1h, v1 - v1h);
        }

        // ---- layer 1 ----
        float c1[8][4];
        #pragma unroll
        for (int nt = 0; nt < 8; nt++) {
            const uint4 w = sW1f[nt][lane];
            float d0 = 0.f, d1 = 0.f, d2 = 0.f, d3 = 0.f;
            mma16816(d0, d1, d2, d3, a1h0, a1h1, 0u, 0u, w.x, w.y, d0, d1, d2, d3);
            mma16816(d0, d1, d2, d3, a1h0, a1h1, 0u, 0u, w.z, w.w, d0, d1, d2, d3);
            mma16816(d0, d1, d2, d3, a1l0, a1l1, 0u, 0u, w.x, w.y, d0, d1, d2, d3);
            c1[nt][0] = fmaxf(d0, 0.f); c1[nt][1] = fmaxf(d1, 0.f);
            c1[nt][2] = fmaxf(d2, 0.f); c1[nt][3] = fmaxf(d3, 0.f);
        }

        // ---- pack h into A2 fragments (C layout == A layout, no shuffles) ----
        unsigned a2h[4][4], a2l[4][4];
        #pragma unroll
        for (int kt = 0; kt < 4; kt++) {
            #pragma unroll
            for (int r = 0; r < 4; r++) {
                const int nt = 2 * kt + (r >> 1);
                const float e0 = c1[nt][(r & 1) ? 2 : 0];
                const float e1 = c1[nt][(r & 1) ? 3 : 1];
                const float e0h = f16_round(e0), e1h = f16_round(e1);
                a2h[kt][r] = f16x2_of(e0h, e1h);
                a2l[kt][r] = f16x2_of(e0 - e0h, e1 - e1h);
            }
        }

        // ---- layer 2 ----
        float c2[8][4];
        #pragma unroll
        for (int nt = 0; nt < 8; nt++) { c2[nt][0] = c2[nt][1] = c2[nt][2] = c2[nt][3] = 0.f; }
        #pragma unroll
        for (int kt = 0; kt < 4; kt++) {
            #pragma unroll
            for (int nt = 0; nt < 8; nt++) {
                const uint4 w = sW2f[kt * 8 + nt][lane];
                mma16816(c2[nt][0], c2[nt][1], c2[nt][2], c2[nt][3],
                         a2h[kt][0], a2h[kt][1], a2h[kt][2], a2h[kt][3], w.x, w.y,
                         c2[nt][0], c2[nt][1], c2[nt][2], c2[nt][3]);
                mma16816(c2[nt][0], c2[nt][1], c2[nt][2], c2[nt][3],
                         a2h[kt][0], a2h[kt][1], a2h[kt][2], a2h[kt][3], w.z, w.w,
                         c2[nt][0], c2[nt][1], c2[nt][2], c2[nt][3]);
                mma16816(c2[nt][0], c2[nt][1], c2[nt][2], c2[nt][3],
                         a2l[kt][0], a2l[kt][1], a2l[kt][2], a2l[kt][3], w.x, w.y,
                         c2[nt][0], c2[nt][1], c2[nt][2], c2[nt][3]);
            }
        }

        // ---- +b2, relu, pack y into A3 fragments ----
        float y[8][4];
        #pragma unroll
        for (int nt = 0; nt < 8; nt++) {
            const float2 bb = *(const float2*)&s_b2[nt * 8 + 2 * q];
            y[nt][0] = fmaxf(c2[nt][0] + bb.x, 0.f);
            y[nt][1] = fmaxf(c2[nt][1] + bb.y, 0.f);
            y[nt][2] = fmaxf(c2[nt][2] + bb.x, 0.f);
            y[nt][3] = fmaxf(c2[nt][3] + bb.y, 0.f);
        }
        unsigned a3h[4][4], a3l[4][4];
        #pragma unroll
        for (int kt = 0; kt < 4; kt++) {
            #pragma unroll
            for (int r = 0; r < 4; r++) {
                const int nt = 2 * kt + (r >> 1);
                const float e0 = y[nt][(r & 1) ? 2 : 0];
                const float e1 = y[nt][(r & 1) ? 3 : 1];
                const float e0h = f16_round(e0), e1h = f16_round(e1);
                a3h[kt][r] = f16x2_of(e0h, e1h);
                a3l[kt][r] = f16x2_of(e0 - e0h, e1 - e1h);
            }
        }

        // ---- heads ----
        float o0 = 0.f, o1 = 0.f, o2 = 0.f, o3 = 0.f;
        #pragma unroll
        for (int kt = 0; kt < 4; kt++) {
            const uint4 w = sB3f[kt][lane];
            mma16816(o0, o1, o2, o3, a3h[kt][0], a3h[kt][1], a3h[kt][2], a3h[kt][3],
                     w.x, w.y, o0, o1, o2, o3);
            mma16816(o0, o1, o2, o3, a3h[kt][0], a3h[kt][1], a3h[kt][2], a3h[kt][3],
                     w.z, w.w, o0, o1, o2, o3);
            mma16816(o0, o1, o2, o3, a3l[kt][0], a3l[kt][1], a3l[kt][2], a3l[kt][3],
                     w.x, w.y, o0, o1, o2, o3);
        }

        // ---- epilogue: q=0 holds (sig,cr), q=1 holds (cg,cb); rows gr, gr+8 ----
        const float p0 = __shfl_xor_sync(0xffffffffu, o0, 1);
        const float p1 = __shfl_xor_sync(0xffffffffu, o1, 1);
        const float p2 = __shfl_xor_sync(0xffffffffu, o2, 1);
        const float p3 = __shfl_xor_sync(0xffffffffu, o3, 1);
        if (q == 0) {
            #pragma unroll
            for (int half = 0; half < 2; half++) {
                const int i = base + gr + half * 8;
                if (i < cnt) {
                    const float sig = (half ? o2 : o0) + s_bias4[0];
                    const float cr  = (half ? o3 : o1) + s_bias4[1];
                    const float cg  = (half ? p2 : p0) + s_bias4[2];
                    const float cb  = (half ? p3 : p1) + s_bias4[3];
                    const int id = __float_as_int(P[i * 4 + 3]);
                    const int ray = id >> 7;
                    const float step = (__ldg(&far_[ray]) - __ldg(&near_[ray])) * (1.0f / (float)S);
                    const float tau = fmaxf(sig, 0.0f) * step;
                    const float alpha = 1.0f - __expf(-tau);
                    const float r = __fdividef(1.0f, 1.0f + __expf(-cr));
                    const float g = __fdividef(1.0f, 1.0f + __expf(-cg));
                    const float b = __fdividef(1.0f, 1.0f + __expf(-cb));
                    g_rgba[id] = make_float4(r, g, b, alpha);
                }
            }
        }
    }
}

// ================= kernel 3: per-ray alpha composite =================
__global__ void __launch_bounds__(256) composite_kernel(
    float* __restrict__ out, int nrays)
{
    const int tid = threadIdx.x;
    const int wid = tid >> 5;
    const int lane = tid & 31;
    const int ray = blockIdx.x * 8 + wid;
    if (ray >= nrays) return;

    const float4* rp = &g_rgba[ray << 7];

    float4 v[4];
    float ta[4];
    float pl = 1.0f;
    #pragma unroll
    for (int q = 0; q < 4; q++) {
        v[q] = rp[lane * 4 + q];
        ta[q] = 1.0f - v[q].w + 1e-10f;
        pl *= ta[q];
    }
    float inc = pl;
    #pragma unroll
    for (int off = 1; off < 32; off <<= 1) {
        const float t = __shfl_up_sync(0xffffffffu, inc, off);
        if (lane >= off) inc *= t;
    }
    const float total = __shfl_sync(0xffffffffu, inc, 31);
    float pre = __shfl_up_sync(0xffffffffu, inc, 1);
    if (lane == 0) pre = 1.0f;

    float T = pre, acr = 0.0f, acg = 0.0f, acb = 0.0f;
    #pragma unroll
    for (int q = 0; q < 4; q++) {
        const float w = v[q].w * T;
        acr = fmaf(w, v[q].x, acr);
        acg = fmaf(w, v[q].y, acg);
        acb = fmaf(w, v[q].z, acb);
        T *= ta[q];
    }
    #pragma unroll
    for (int off = 16; off >= 1; off >>= 1) {
        acr += __shfl_xor_sync(0xffffffffu, acr, off);
        acg += __shfl_xor_sync(0xffffffffu, acg, off);
        acb += __shfl_xor_sync(0xffffffffu, acb, off);
    }
    if (lane == 0) {
        out[ray * 3 + 0] = acr + total;
        out[ray * 3 + 1] = acg + total;
        out[ray * 3 + 2] = acb + total;
    }
}

extern "C" void kernel_launch(void* const* d_in, const int* in_sizes, int n_in,
                              void* d_out, int out_size) {
    const float* rays_o  = (const float*)d_in[0];
    const float* rays_d  = (const float*)d_in[1];
    const float* near_   = (const float*)d_in[2];
    const float* far_    = (const float*)d_in[3];
    const float* jitter  = (const float*)d_in[4];
    const float* density = (const float*)d_in[5];
    const float* W1      = (const float*)d_in[6];
    const float* b1      = (const float*)d_in[7];
    const float* W2      = (const float*)d_in[8];
    const float* b2      = (const float*)d_in[9];
    const float* Wsig    = (const float*)d_in[10];
    const float* bsig    = (const float*)d_in[11];
    const float* Wrgb    = (const float*)d_in[12];
    const float* brgb    = (const float*)d_in[13];
    float* out = (float*)d_out;

    const int nrays = in_sizes[2];

    reset_ctr_kernel<<<1, 1>>>();
    compact_kernel<<<(nrays + 1) / 2, 256>>>(rays_o, rays_d, near_, far_,
                                             jitter, density, nrays);
    mlp_kernel<<<MLP_GRID, MLP_BLK>>>(near_, far_, W1, b1, W2, b2,
                                      Wsig, bsig, Wrgb, brgb);
    composite_kernel<<<(nrays + 7) / 8, 256>>>(out, nrays);
}

// round 12
// speedup vs baseline: 2.6203x; 1.0274x over previous
#include <cuda_runtime.h>

#define S 128
#define H 64
#define GRIDR 64
#define NMAX 8192
#define MLP_GRID 444
#define MLP_BLK 128

__device__ int    g_cnt;
__device__ float4 g_pts[NMAX * S];    // (px,py,pz, id-as-float-bits)
__device__ float4 g_rgba[NMAX * S];   // (r,g,b,alpha)

__global__ void reset_ctr_kernel() { g_cnt = 0; }

// ---- f16 helpers ----
__device__ __forceinline__ float f16_round(float v) {
    unsigned short h;
    asm("cvt.rn.f16.f32 %0, %1;" : "=h"(h) : "f"(v));
    float r;
    asm("cvt.f32.f16 %0, %1;" : "=f"(r) : "h"(h));
    return r;
}
// pack two floats to f16x2: LOW half = first arg (lower index element)
__device__ __forceinline__ unsigned f16x2_of(float lo_v, float hi_v) {
    unsigned r;
    asm("cvt.rn.f16x2.f32 %0, %1, %2;" : "=r"(r) : "f"(hi_v), "f"(lo_v));
    return r;
}
__device__ __forceinline__ void mma16816(
    float& d0, float& d1, float& d2, float& d3,
    unsigned a0, unsigned a1, unsigned a2, unsigned a3,
    unsigned b0, unsigned b1,
    float c0, float c1, float c2, float c3)
{
    asm("mma.sync.aligned.m16n8k16.row.col.f32.f16.f16.f32 "
        "{%0,%1,%2,%3}, {%4,%5,%6,%7}, {%8,%9}, {%10,%11,%12,%13};"
        : "=f"(d0), "=f"(d1), "=f"(d2), "=f"(d3)
        : "r"(a0), "r"(a1), "r"(a2), "r"(a3), "r"(b0), "r"(b1),
          "f"(c0), "f"(c1), "f"(c2), "f"(c3));
}

// ================= kernel 1: occupancy test + global compaction =================
__global__ void __launch_bounds__(256) compact_kernel(
    const float* __restrict__ rays_o, const float* __restrict__ rays_d,
    const float* __restrict__ near_, const float* __restrict__ far_,
    const float* __restrict__ jitter, const float* __restrict__ density,
    int nrays)
{
    __shared__ int warp_base[8];

    const int tid = threadIdx.x;
    const int q   = tid >> 7;
    const int s   = tid & 127;
    const int ray = blockIdx.x * 2 + q;
    const int wid = tid >> 5;
    const int lane = tid & 31;

    bool active = false;
    float px = 0.f, py = 0.f, pz = 0.f;
    int id = 0;

    if (ray < nrays) {
        const float ox = rays_o[ray * 3 + 0], oy = rays_o[ray * 3 + 1], oz = rays_o[ray * 3 + 2];
        const float dx = rays_d[ray * 3 + 0], dy = rays_d[ray * 3 + 1], dz = rays_d[ray * 3 + 2];
        const float nr = near_[ray], fr = far_[ray];
        const float step = (fr - nr) * (1.0f / (float)S);

        const float z = nr + (float)s * step;
        const float px0 = ox + z * dx;
        const float py0 = oy + z * dy;
        const float pz0 = oz + z * dz;
        const float fx = ((px0 + 1.25f) * 0.4f) * 64.0f;
        const float fy = ((py0 + 1.55f) * 0.4f) * 64.0f;
        const float fz = ((pz0 + 1.25f) * 0.4f) * 64.0f;
        const int ix = (int)floorf(fx);
        const int iy = (int)floorf(fy);
        const int iz = (int)floorf(fz);
        const bool inb = (ix >= 0) & (ix < GRIDR) & (iy >= 0) & (iy < GRIDR) &
                         (iz >= 0) & (iz < GRIDR);
        if (inb) active = __ldg(&density[(ix * GRIDR + iy) * GRIDR + iz]) > 0.5f;

        float zv = active ? z : 0.0f;
        zv += jitter[ray * S + s] * step;

        px = ox + zv * dx;
        py = oy + zv * dy;
        pz = oz + zv * dz;
        id = (ray << 7) | s;

        g_rgba[id] = make_float4(0.f, 0.f, 0.f, 0.f);
    }

    const unsigned ballot = __ballot_sync(0xffffffffu, active);
    if (lane == 0) warp_base[wid] = __popc(ballot);
    __syncthreads();
    if (tid == 0) {
        int sum = 0;
        #pragma unroll
        for (int w = 0; w < 8; w++) { int c = warp_base[w]; warp_base[w] = sum; sum += c; }
        const int base = atomicAdd(&g_cnt, sum);
        #pragma unroll
        for (int w = 0; w < 8; w++) warp_base[w] += base;
    }
    __syncthreads();
    if (active) {
        const int idx = warp_base[wid] + __popc(ballot & ((1u << lane) - 1u));
        g_pts[idx] = make_float4(px, py, pz, __int_as_float(id));
    }
}

// ================= kernel 2: tensor-core MLP over compacted samples =================
// Per warp-iteration: 16 samples (M), chained m16n8k16 f16 mma, hi/lo 3-mma for accuracy.
__global__ void __launch_bounds__(MLP_BLK, 3) mlp_kernel(
    const float* __restrict__ near_, const float* __restrict__ far_,
    const float* __restrict__ W1, const float* __restrict__ b1,
    const float* __restrict__ W2, const float* __restrict__ b2,
    const float* __restrict__ Wsig, const float* __restrict__ bsig,
    const float* __restrict__ Wrgb, const float* __restrict__ brgb)
{
    // weight fragments, pre-packed: uint4 = {b0_hi, b1_hi, b0_lo, b1_lo}
    __shared__ __align__(16) uint4 sW1f[8][32];    // layer1: kt=0, nt=0..7
    __shared__ __align__(16) uint4 sW2f[32][32];   // layer2: [kt*8+nt]
    __shared__ __align__(16) uint4 sB3f[4][32];    // heads:  kt=0..3, nt=0
    __shared__ float s_b2[H];
    __shared__ float s_bias4[4];                   // bsig, brgb[0..2]

    const int tid = threadIdx.x;

    // ---- prepack weights into fragment order ----
    for (int e = tid; e < 44 * 32; e += MLP_BLK) {
        const int lane = e & 31, tile = e >> 5;
        const int q = lane & 3, gr = lane >> 2;
        float v[4];
        if (tile < 8) {                      // B1[16][64]: rows 0-2 = W1, row3 = b1, rest 0
            const int n = tile * 8 + gr;
            #pragma unroll
            for (int j = 0; j < 4; j++) {
                const int k = ((j >> 1) << 3) + 2 * q + (j & 1);
                v[j] = (k < 3) ? W1[k * H + n] : (k == 3 ? b1[n] : 0.0f);
            }
        } else if (tile < 40) {              // B2 = W2[64][64]
            const int t = tile - 8;
            const int kt = t >> 3, nt = t & 7;
            const int n = nt * 8 + gr;
            #pragma unroll
            for (int j = 0; j < 4; j++) {
                const int k = kt * 16 + ((j >> 1) << 3) + 2 * q + (j & 1);
                v[j] = W2[k * H + n];
            }
        } else {                             // B3[64][8]: col0 Wsig, cols1-3 Wrgb, rest 0
            const int kt = tile - 40;
            const int n = gr;
            #pragma unroll
            for (int j = 0; j < 4; j++) {
                const int k = kt * 16 + ((j >> 1) << 3) + 2 * q + (j & 1);
                v[j] = (n == 0) ? Wsig[k] : (n < 4 ? Wrgb[k * 3 + (n - 1)] : 0.0f);
            }
        }
        const float h0 = f16_round(v[0]), h1v = f16_round(v[1]);
        const float h2 = f16_round(v[2]), h3v = f16_round(v[3]);
        uint4 pk;
        pk.x = f16x2_of(h0, h1v);
        pk.y = f16x2_of(h2, h3v);
        pk.z = f16x2_of(v[0] - h0, v[1] - h1v);
        pk.w = f16x2_of(v[2] - h2, v[3] - h3v);
        if (tile < 8)       sW1f[tile][lane] = pk;
        else if (tile < 40) sW2f[tile - 8][lane] = pk;
        else                sB3f[tile - 40][lane] = pk;
    }
    for (int i = tid; i < H; i += MLP_BLK) s_b2[i] = b2[i];
    if (tid == 0) {
        s_bias4[0] = bsig[0]; s_bias4[1] = brgb[0];
        s_bias4[2] = brgb[1]; s_bias4[3] = brgb[2];
    }
    __syncthreads();

    const int cnt = g_cnt;
    const int warp = tid >> 5, lane = tid & 31;
    const int q = lane & 3, gr = lane >> 2;
    const float* P = (const float*)g_pts;
    const int stride = gridDim.x * 4 * 16;

    for (int base = (blockIdx.x * 4 + warp) * 16; base < cnt; base += stride) {
        const int i0 = min(base + gr, cnt - 1);
        const int i1 = min(base + gr + 8, cnt - 1);

        // ---- A1 fragment: P[16 samples][16] = (px,py,pz,1, 0...) ----
        unsigned a1h0 = 0, a1h1 = 0, a1l0 = 0, a1l1 = 0;
        if (q < 2) {
            float u0, v0, u1, v1;
            if (q == 0) {
                float2 t0 = *(const float2*)&P[i0 * 4];
                float2 t1 = *(const float2*)&P[i1 * 4];
                u0 = t0.x; v0 = t0.y; u1 = t1.x; v1 = t1.y;
            } else {
                u0 = P[i0 * 4 + 2]; v0 = 1.0f;
                u1 = P[i1 * 4 + 2]; v1 = 1.0f;
            }
            const float u0h = f16_round(u0), v0h = f16_round(v0);
            const float u1h = f16_round(u1), v1h = f16_round(v1);
            a1h0 = f16x2_of(u0h, v0h);  a1l0 = f16x2_of(u0 - u0h, v0 - v0h);
            a1h1 = f16x2_of(u1h, v1h);  a1l1 = f16x2_of(u1 - u1h, v1 - v1h);
        }

        // ---- layer 1 ----
        float c1[8][4];
        #pragma unroll
        for (int nt = 0; nt < 8; nt++) {
            const uint4 w = sW1f[nt][lane];
            float d0 = 0.f, d1 = 0.f, d2 = 0.f, d3 = 0.f;
            mma16816(d0, d1, d2, d3, a1h0, a1h1, 0u, 0u, w.x, w.y, d0, d1, d2, d3);
            mma16816(d0, d1, d2, d3, a1h0, a1h1, 0u, 0u, w.z, w.w, d0, d1, d2, d3);
            mma16816(d0, d1, d2, d3, a1l0, a1l1, 0u, 0u, w.x, w.y, d0, d1, d2, d3);
            c1[nt][0] = fmaxf(d0, 0.f); c1[nt][1] = fmaxf(d1, 0.f);
            c1[nt][2] = fmaxf(d2, 0.f); c1[nt][3] = fmaxf(d3, 0.f);
        }

        // ---- pack h into A2 fragments (C layout == A layout, no shuffles) ----
        unsigned a2h[4][4], a2l[4][4];
        #pragma unroll
        for (int kt = 0; kt < 4; kt++) {
            #pragma unroll
            for (int r = 0; r < 4; r++) {
                const int nt = 2 * kt + (r >> 1);
                const float e0 = c1[nt][(r & 1) ? 2 : 0];
                const float e1 = c1[nt][(r & 1) ? 3 : 1];
                const float e0h = f16_round(e0), e1h = f16_round(e1);
                a2h[kt][r] = f16x2_of(e0h, e1h);
                a2l[kt][r] = f16x2_of(e0 - e0h, e1 - e1h);
            }
        }

        // ---- layer 2 ----
        float c2[8][4];
        #pragma unroll
        for (int nt = 0; nt < 8; nt++) { c2[nt][0] = c2[nt][1] = c2[nt][2] = c2[nt][3] = 0.f; }
        #pragma unroll
        for (int kt = 0; kt < 4; kt++) {
            #pragma unroll
            for (int nt = 0; nt < 8; nt++) {
                const uint4 w = sW2f[kt * 8 + nt][lane];
                mma16816(c2[nt][0], c2[nt][1], c2[nt][2], c2[nt][3],
                         a2h[kt][0], a2h[kt][1], a2h[kt][2], a2h[kt][3], w.x, w.y,
                         c2[nt][0], c2[nt][1], c2[nt][2], c2[nt][3]);
                mma16816(c2[nt][0], c2[nt][1], c2[nt][2], c2[nt][3],
                         a2h[kt][0], a2h[kt][1], a2h[kt][2], a2h[kt][3], w.z, w.w,
                         c2[nt][0], c2[nt][1], c2[nt][2], c2[nt][3]);
                mma16816(c2[nt][0], c2[nt][1], c2[nt][2], c2[nt][3],
                         a2l[kt][0], a2l[kt][1], a2l[kt][2], a2l[kt][3], w.x, w.y,
                         c2[nt][0], c2[nt][1], c2[nt][2], c2[nt][3]);
            }
        }

        // ---- +b2, relu, pack y into A3 fragments ----
        float y[8][4];
        #pragma unroll
        for (int nt = 0; nt < 8; nt++) {
            const float2 bb = *(const float2*)&s_b2[nt * 8 + 2 * q];
            y[nt][0] = fmaxf(c2[nt][0] + bb.x, 0.f);
            y[nt][1] = fmaxf(c2[nt][1] + bb.y, 0.f);
            y[nt][2] = fmaxf(c2[nt][2] + bb.x, 0.f);
            y[nt][3] = fmaxf(c2[nt][3] + bb.y, 0.f);
        }
        unsigned a3h[4][4], a3l[4][4];
        #pragma unroll
        for (int kt = 0; kt < 4; kt++) {
            #pragma unroll
            for (int r = 0; r < 4; r++) {
                const int nt = 2 * kt + (r >> 1);
                const float e0 = y[nt][(r & 1) ? 2 : 0];
                const float e1 = y[nt][(r & 1) ? 3 : 1];
                const float e0h = f16_round(e0), e1h = f16_round(e1);
                a3h[kt][r] = f16x2_of(e0h, e1h);
                a3l[kt][r] = f16x2_of(e0 - e0h, e1 - e1h);
            }
        }

        // ---- heads ----
        float o0 = 0.f, o1 = 0.f, o2 = 0.f, o3 = 0.f;
        #pragma unroll
        for (int kt = 0; kt < 4; kt++) {
            const uint4 w = sB3f[kt][lane];
            mma16816(o0, o1, o2, o3, a3h[kt][0], a3h[kt][1], a3h[kt][2], a3h[kt][3],
                     w.x, w.y, o0, o1, o2, o3);
            mma16816(o0, o1, o2, o3, a3h[kt][0], a3h[kt][1], a3h[kt][2], a3h[kt][3],
                     w.z, w.w, o0, o1, o2, o3);
            mma16816(o0, o1, o2, o3, a3l[kt][0], a3l[kt][1], a3l[kt][2], a3l[kt][3],
                     w.x, w.y, o0, o1, o2, o3);
        }

        // ---- epilogue: q=0 holds (sig,cr), q=1 holds (cg,cb); rows gr, gr+8 ----
        const float p0 = __shfl_xor_sync(0xffffffffu, o0, 1);
        const float p1 = __shfl_xor_sync(0xffffffffu, o1, 1);
        const float p2 = __shfl_xor_sync(0xffffffffu, o2, 1);
        const float p3 = __shfl_xor_sync(0xffffffffu, o3, 1);
        if (q == 0) {
            #pragma unroll
            for (int half = 0; half < 2; half++) {
                const int i = base + gr + half * 8;
                if (i < cnt) {
                    const float sig = (half ? o2 : o0) + s_bias4[0];
                    const float cr  = (half ? o3 : o1) + s_bias4[1];
                    const float cg  = (half ? p2 : p0) + s_bias4[2];
                    const float cb  = (half ? p3 : p1) + s_bias4[3];
                    const int id = __float_as_int(P[i * 4 + 3]);
                    const int ray = id >> 7;
                    const float step = (__ldg(&far_[ray]) - __ldg(&near_[ray])) * (1.0f / (float)S);
                    const float tau = fmaxf(sig, 0.0f) * step;
                    const float alpha = 1.0f - __expf(-tau);
                    const float r = __fdividef(1.0f, 1.0f + __expf(-cr));
                    const float g = __fdividef(1.0f, 1.0f + __expf(-cg));
                    const float b = __fdividef(1.0f, 1.0f + __expf(-cb));
                    g_rgba[id] = make_float4(r, g, b, alpha);
                }
            }
        }
    }
}

// ================= kernel 3: per-ray alpha composite =================
__global__ void __launch_bounds__(256) composite_kernel(
    float* __restrict__ out, int nrays)
{
    const int tid = threadIdx.x;
    const int wid = tid >> 5;
    const int lane = tid & 31;
    const int ray = blockIdx.x * 8 + wid;
    if (ray >= nrays) return;

    const float4* rp = &g_rgba[ray << 7];

    float4 v[4];
    float ta[4];
    float pl = 1.0f;
    #pragma unroll
    for (int q = 0; q < 4; q++) {
        v[q] = rp[lane * 4 + q];
        ta[q] = 1.0f - v[q].w + 1e-10f;
        pl *= ta[q];
    }
    float inc = pl;
    #pragma unroll
    for (int off = 1; off < 32; off <<= 1) {
        const float t = __shfl_up_sync(0xffffffffu, inc, off);
        if (lane >= off) inc *= t;
    }
    const float total = __shfl_sync(0xffffffffu, inc, 31);
    float pre = __shfl_up_sync(0xffffffffu, inc, 1);
    if (lane == 0) pre = 1.0f;

    float T = pre, acr = 0.0f, acg = 0.0f, acb = 0.0f;
    #pragma unroll
    for (int q = 0; q < 4; q++) {
        const float w = v[q].w * T;
        acr = fmaf(w, v[q].x, acr);
        acg = fmaf(w, v[q].y, acg);
        acb = fmaf(w, v[q].z, acb);
        T *= ta[q];
    }
    #pragma unroll
    for (int off = 16; off >= 1; off >>= 1) {
        acr += __shfl_xor_sync(0xffffffffu, acr, off);
        acg += __shfl_xor_sync(0xffffffffu, acg, off);
        acb += __shfl_xor_sync(0xffffffffu, acb, off);
    }
    if (lane == 0) {
        out[ray * 3 + 0] = acr + total;
        out[ray * 3 + 1] = acg + total;
        out[ray * 3 + 2] = acb + total;
    }
}

extern "C" void kernel_launch(void* const* d_in, const int* in_sizes, int n_in,
                              void* d_out, int out_size) {
    const float* rays_o  = (const float*)d_in[0];
    const float* rays_d  = (const float*)d_in[1];
    const float* near_   = (const float*)d_in[2];
    const float* far_    = (const float*)d_in[3];
    const float* jitter  = (const float*)d_in[4];
    const float* density = (const float*)d_in[5];
    const float* W1      = (const float*)d_in[6];
    const float* b1      = (const float*)d_in[7];
    const float* W2      = (const float*)d_in[8];
    const float* b2      = (const float*)d_in[9];
    const float* Wsig    = (const float*)d_in[10];
    const float* bsig    = (const float*)d_in[11];
    const float* Wrgb    = (const float*)d_in[12];
    const float* brgb    = (const float*)d_in[13];
    float* out = (float*)d_out;

    const int nrays = in_sizes[2];

    reset_ctr_kernel<<<1, 1>>>();
    compact_kernel<<<(nrays + 1) / 2, 256>>>(rays_o, rays_d, near_, far_,
                                             jitter, density, nrays);
    mlp_kernel<<<MLP_GRID, MLP_BLK>>>(near_, far_, W1, b1, W2, b2,
                                      Wsig, bsig, Wrgb, brgb);
    composite_kernel<<<(nrays + 7) / 8, 256>>>(out, nrays);
}

// round 13
// speedup vs baseline: 2.7147x; 1.0360x over previous
#include <cuda_runtime.h>

#define S 128
#define H 64
#define GRIDR 64
#define NMAX 8192
#define MLP_GRID 444
#define MLP_BLK 128

__device__ int      g_cnt;                 // statically zero-initialized; composite re-zeros each run
__device__ float4   g_pts[NMAX * S];       // (px,py,pz, id-as-float-bits)
__device__ float4   g_rgba[NMAX * S];      // (r,g,b,alpha) — only active slots written
__device__ unsigned g_mask[NMAX * 4];      // 128-bit active mask per ray

// ---- f16 helpers ----
__device__ __forceinline__ float f16_round(float v) {
    unsigned short h;
    asm("cvt.rn.f16.f32 %0, %1;" : "=h"(h) : "f"(v));
    float r;
    asm("cvt.f32.f16 %0, %1;" : "=f"(r) : "h"(h));
    return r;
}
// pack two floats to f16x2: LOW half = first arg (lower index element)
__device__ __forceinline__ unsigned f16x2_of(float lo_v, float hi_v) {
    unsigned r;
    asm("cvt.rn.f16x2.f32 %0, %1, %2;" : "=r"(r) : "f"(hi_v), "f"(lo_v));
    return r;
}
__device__ __forceinline__ void mma16816(
    float& d0, float& d1, float& d2, float& d3,
    unsigned a0, unsigned a1, unsigned a2, unsigned a3,
    unsigned b0, unsigned b1,
    float c0, float c1, float c2, float c3)
{
    asm("mma.sync.aligned.m16n8k16.row.col.f32.f16.f16.f32 "
        "{%0,%1,%2,%3}, {%4,%5,%6,%7}, {%8,%9}, {%10,%11,%12,%13};"
        : "=f"(d0), "=f"(d1), "=f"(d2), "=f"(d3)
        : "r"(a0), "r"(a1), "r"(a2), "r"(a3), "r"(b0), "r"(b1),
          "f"(c0), "f"(c1), "f"(c2), "f"(c3));
}

// ================= kernel 1: occupancy test + global compaction + mask =================
__global__ void __launch_bounds__(256) compact_kernel(
    const float* __restrict__ rays_o, const float* __restrict__ rays_d,
    const float* __restrict__ near_, const float* __restrict__ far_,
    const float* __restrict__ jitter, const float* __restrict__ density,
    int nrays)
{
    __shared__ int warp_base[8];

    const int tid = threadIdx.x;
    const int q   = tid >> 7;
    const int s   = tid & 127;
    const int ray = blockIdx.x * 2 + q;
    const int wid = tid >> 5;
    const int lane = tid & 31;

    bool active = false;
    float px = 0.f, py = 0.f, pz = 0.f;
    int id = 0;

    if (ray < nrays) {
        const float ox = rays_o[ray * 3 + 0], oy = rays_o[ray * 3 + 1], oz = rays_o[ray * 3 + 2];
        const float dx = rays_d[ray * 3 + 0], dy = rays_d[ray * 3 + 1], dz = rays_d[ray * 3 + 2];
        const float nr = near_[ray], fr = far_[ray];
        const float step = (fr - nr) * (1.0f / (float)S);

        const float z = nr + (float)s * step;
        const float px0 = ox + z * dx;
        const float py0 = oy + z * dy;
        const float pz0 = oz + z * dz;
        const float fx = ((px0 + 1.25f) * 0.4f) * 64.0f;
        const float fy = ((py0 + 1.55f) * 0.4f) * 64.0f;
        const float fz = ((pz0 + 1.25f) * 0.4f) * 64.0f;
        const int ix = (int)floorf(fx);
        const int iy = (int)floorf(fy);
        const int iz = (int)floorf(fz);
        const bool inb = (ix >= 0) & (ix < GRIDR) & (iy >= 0) & (iy < GRIDR) &
                         (iz >= 0) & (iz < GRIDR);
        if (inb) active = __ldg(&density[(ix * GRIDR + iy) * GRIDR + iz]) > 0.5f;

        float zv = active ? z : 0.0f;
        zv += jitter[ray * S + s] * step;

        px = ox + zv * dx;
        py = oy + zv * dy;
        pz = oz + zv * dz;
        id = (ray << 7) | s;
    }

    const unsigned ballot = __ballot_sync(0xffffffffu, active);
    // per-ray 128-bit active mask: word (wid&3) covers samples [(wid&3)*32, +32)
    if (lane == 0 && ray < nrays) g_mask[ray * 4 + (wid & 3)] = ballot;

    if (lane == 0) warp_base[wid] = __popc(ballot);
    __syncthreads();
    if (tid == 0) {
        int sum = 0;
        #pragma unroll
        for (int w = 0; w < 8; w++) { int c = warp_base[w]; warp_base[w] = sum; sum += c; }
        const int base = atomicAdd(&g_cnt, sum);
        #pragma unroll
        for (int w = 0; w < 8; w++) warp_base[w] += base;
    }
    __syncthreads();
    if (active) {
        const int idx = warp_base[wid] + __popc(ballot & ((1u << lane) - 1u));
        g_pts[idx] = make_float4(px, py, pz, __int_as_float(id));
    }
}

// ================= kernel 2: tensor-core MLP over compacted samples =================
__global__ void __launch_bounds__(MLP_BLK, 3) mlp_kernel(
    const float* __restrict__ near_, const float* __restrict__ far_,
    const float* __restrict__ W1, const float* __restrict__ b1,
    const float* __restrict__ W2, const float* __restrict__ b2,
    const float* __restrict__ Wsig, const float* __restrict__ bsig,
    const float* __restrict__ Wrgb, const float* __restrict__ brgb)
{
    __shared__ __align__(16) uint4 sW1f[8][32];
    __shared__ __align__(16) uint4 sW2f[32][32];
    __shared__ __align__(16) uint4 sB3f[4][32];
    __shared__ float s_b2[H];
    __shared__ float s_bias4[4];

    const int tid = threadIdx.x;

    for (int e = tid; e < 44 * 32; e += MLP_BLK) {
        const int lane = e & 31, tile = e >> 5;
        const int q = lane & 3, gr = lane >> 2;
        float v[4];
        if (tile < 8) {
            const int n = tile * 8 + gr;
            #pragma unroll
            for (int j = 0; j < 4; j++) {
                const int k = ((j >> 1) << 3) + 2 * q + (j & 1);
                v[j] = (k < 3) ? W1[k * H + n] : (k == 3 ? b1[n] : 0.0f);
            }
        } else if (tile < 40) {
            const int t = tile - 8;
            const int kt = t >> 3, nt = t & 7;
            const int n = nt * 8 + gr;
            #pragma unroll
            for (int j = 0; j < 4; j++) {
                const int k = kt * 16 + ((j >> 1) << 3) + 2 * q + (j & 1);
                v[j] = W2[k * H + n];
            }
        } else {
            const int kt = tile - 40;
            const int n = gr;
            #pragma unroll
            for (int j = 0; j < 4; j++) {
                const int k = kt * 16 + ((j >> 1) << 3) + 2 * q + (j & 1);
                v[j] = (n == 0) ? Wsig[k] : (n < 4 ? Wrgb[k * 3 + (n - 1)] : 0.0f);
            }
        }
        const float h0 = f16_round(v[0]), h1v = f16_round(v[1]);
        const float h2 = f16_round(v[2]), h3v = f16_round(v[3]);
        uint4 pk;
        pk.x = f16x2_of(h0, h1v);
        pk.y = f16x2_of(h2, h3v);
        pk.z = f16x2_of(v[0] - h0, v[1] - h1v);
        pk.w = f16x2_of(v[2] - h2, v[3] - h3v);
        if (tile < 8)       sW1f[tile][lane] = pk;
        else if (tile < 40) sW2f[tile - 8][lane] = pk;
        else                sB3f[tile - 40][lane] = pk;
    }
    for (int i = tid; i < H; i += MLP_BLK) s_b2[i] = b2[i];
    if (tid == 0) {
        s_bias4[0] = bsig[0]; s_bias4[1] = brgb[0];
        s_bias4[2] = brgb[1]; s_bias4[3] = brgb[2];
    }
    __syncthreads();

    const int cnt = g_cnt;
    const int warp = tid >> 5, lane = tid & 31;
    const int q = lane & 3, gr = lane >> 2;
    const float* P = (const float*)g_pts;
    const int stride = gridDim.x * 4 * 16;

    for (int base = (blockIdx.x * 4 + warp) * 16; base < cnt; base += stride) {
        const int i0 = min(base + gr, cnt - 1);
        const int i1 = min(base + gr + 8, cnt - 1);

        unsigned a1h0 = 0, a1h1 = 0, a1l0 = 0, a1l1 = 0;
        if (q < 2) {
            float u0, v0, u1, v1;
            if (q == 0) {
                float2 t0 = *(const float2*)&P[i0 * 4];
                float2 t1 = *(const float2*)&P[i1 * 4];
                u0 = t0.x; v0 = t0.y; u1 = t1.x; v1 = t1.y;
            } else {
                u0 = P[i0 * 4 + 2]; v0 = 1.0f;
                u1 = P[i1 * 4 + 2]; v1 = 1.0f;
            }
            const float u0h = f16_round(u0), v0h = f16_round(v0);
            const float u1h = f16_round(u1), v1h = f16_round(v1);
            a1h0 = f16x2_of(u0h, v0h);  a1l0 = f16x2_of(u0 - u0h, v0 - v0h);
            a1h1 = f16x2_of(u1h, v1h);  a1l1 = f16x2_of(u1 - u1h, v1 - v1h);
        }

        float c1[8][4];
        #pragma unroll
        for (int nt = 0; nt < 8; nt++) {
            const uint4 w = sW1f[nt][lane];
            float d0 = 0.f, d1 = 0.f, d2 = 0.f, d3 = 0.f;
            mma16816(d0, d1, d2, d3, a1h0, a1h1, 0u, 0u, w.x, w.y, d0, d1, d2, d3);
            mma16816(d0, d1, d2, d3, a1h0, a1h1, 0u, 0u, w.z, w.w, d0, d1, d2, d3);
            mma16816(d0, d1, d2, d3, a1l0, a1l1, 0u, 0u, w.x, w.y, d0, d1, d2, d3);
            c1[nt][0] = fmaxf(d0, 0.f); c1[nt][1] = fmaxf(d1, 0.f);
            c1[nt][2] = fmaxf(d2, 0.f); c1[nt][3] = fmaxf(d3, 0.f);
        }

        unsigned a2h[4][4], a2l[4][4];
        #pragma unroll
        for (int kt = 0; kt < 4; kt++) {
            #pragma unroll
            for (int r = 0; r < 4; r++) {
                const int nt = 2 * kt + (r >> 1);
                const float e0 = c1[nt][(r & 1) ? 2 : 0];
                const float e1 = c1[nt][(r & 1) ? 3 : 1];
                const float e0h = f16_round(e0), e1h = f16_round(e1);
                a2h[kt][r] = f16x2_of(e0h, e1h);
                a2l[kt][r] = f16x2_of(e0 - e0h, e1 - e1h);
            }
        }

        float c2[8][4];
        #pragma unroll
        for (int nt = 0; nt < 8; nt++) { c2[nt][0] = c2[nt][1] = c2[nt][2] = c2[nt][3] = 0.f; }
        #pragma unroll
        for (int kt = 0; kt < 4; kt++) {
            #pragma unroll
            for (int nt = 0; nt < 8; nt++) {
                const uint4 w = sW2f[kt * 8 + nt][lane];
                mma16816(c2[nt][0], c2[nt][1], c2[nt][2], c2[nt][3],
                         a2h[kt][0], a2h[kt][1], a2h[kt][2], a2h[kt][3], w.x, w.y,
                         c2[nt][0], c2[nt][1], c2[nt][2], c2[nt][3]);
                mma16816(c2[nt][0], c2[nt][1], c2[nt][2], c2[nt][3],
                         a2h[kt][0], a2h[kt][1], a2h[kt][2], a2h[kt][3], w.z, w.w,
                         c2[nt][0], c2[nt][1], c2[nt][2], c2[nt][3]);
                mma16816(c2[nt][0], c2[nt][1], c2[nt][2], c2[nt][3],
                         a2l[kt][0], a2l[kt][1], a2l[kt][2], a2l[kt][3], w.x, w.y,
                         c2[nt][0], c2[nt][1], c2[nt][2], c2[nt][3]);
            }
        }

        float y[8][4];
        #pragma unroll
        for (int nt = 0; nt < 8; nt++) {
            const float2 bb = *(const float2*)&s_b2[nt * 8 + 2 * q];
            y[nt][0] = fmaxf(c2[nt][0] + bb.x, 0.f);
            y[nt][1] = fmaxf(c2[nt][1] + bb.y, 0.f);
            y[nt][2] = fmaxf(c2[nt][2] + bb.x, 0.f);
            y[nt][3] = fmaxf(c2[nt][3] + bb.y, 0.f);
        }
        unsigned a3h[4][4], a3l[4][4];
        #pragma unroll
        for (int kt = 0; kt < 4; kt++) {
            #pragma unroll
            for (int r = 0; r < 4; r++) {
                const int nt = 2 * kt + (r >> 1);
                const float e0 = y[nt][(r & 1) ? 2 : 0];
                const float e1 = y[nt][(r & 1) ? 3 : 1];
                const float e0h = f16_round(e0), e1h = f16_round(e1);
                a3h[kt][r] = f16x2_of(e0h, e1h);
                a3l[kt][r] = f16x2_of(e0 - e0h, e1 - e1h);
            }
        }

        float o0 = 0.f, o1 = 0.f, o2 = 0.f, o3 = 0.f;
        #pragma unroll
        for (int kt = 0; kt < 4; kt++) {
            const uint4 w = sB3f[kt][lane];
            mma16816(o0, o1, o2, o3, a3h[kt][0], a3h[kt][1], a3h[kt][2], a3h[kt][3],
                     w.x, w.y, o0, o1, o2, o3);
            mma16816(o0, o1, o2, o3, a3h[kt][0], a3h[kt][1], a3h[kt][2], a3h[kt][3],
                     w.z, w.w, o0, o1, o2, o3);
            mma16816(o0, o1, o2, o3, a3l[kt][0], a3l[kt][1], a3l[kt][2], a3l[kt][3],
                     w.x, w.y, o0, o1, o2, o3);
        }

        const float p0 = __shfl_xor_sync(0xffffffffu, o0, 1);
        const float p1 = __shfl_xor_sync(0xffffffffu, o1, 1);
        const float p2 = __shfl_xor_sync(0xffffffffu, o2, 1);
        const float p3 = __shfl_xor_sync(0xffffffffu, o3, 1);
        if (q == 0) {
            #pragma unroll
            for (int half = 0; half < 2; half++) {
                const int i = base + gr + half * 8;
                if (i < cnt) {
                    const float sig = (half ? o2 : o0) + s_bias4[0];
                    const float cr  = (half ? o3 : o1) + s_bias4[1];
                    const float cg  = (half ? p2 : p0) + s_bias4[2];
                    const float cb  = (half ? p3 : p1) + s_bias4[3];
                    const int id = __float_as_int(P[i * 4 + 3]);
                    const int ray = id >> 7;
                    const float step = (__ldg(&far_[ray]) - __ldg(&near_[ray])) * (1.0f / (float)S);
                    const float tau = fmaxf(sig, 0.0f) * step;
                    const float alpha = 1.0f - __expf(-tau);
                    const float r = __fdividef(1.0f, 1.0f + __expf(-cr));
                    const float g = __fdividef(1.0f, 1.0f + __expf(-cg));
                    const float b = __fdividef(1.0f, 1.0f + __expf(-cb));
                    g_rgba[id] = make_float4(r, g, b, alpha);
                }
            }
        }
    }
}

// ================= kernel 3: per-ray masked alpha composite (+ counter reset) =================
__global__ void __launch_bounds__(256) composite_kernel(
    float* __restrict__ out, int nrays)
{
    const int tid = threadIdx.x;
    const int wid = tid >> 5;
    const int lane = tid & 31;
    const int ray = blockIdx.x * 8 + wid;

    // reset the compaction counter for the next graph replay (nobody reads it here)
    if (blockIdx.x == 0 && tid == 0) g_cnt = 0;

    if (ray >= nrays) return;

    const float4* rp = &g_rgba[ray << 7];
    const unsigned m = g_mask[ray * 4 + (lane >> 3)];

    float4 v[4];
    float ta[4];
    float pl = 1.0f;
    #pragma unroll
    for (int q = 0; q < 4; q++) {
        const unsigned bit = ((lane & 7) << 2) + q;
        if ((m >> bit) & 1u) v[q] = rp[lane * 4 + q];
        else                 v[q] = make_float4(0.f, 0.f, 0.f, 0.f);
        ta[q] = 1.0f - v[q].w + 1e-10f;
        pl *= ta[q];
    }
    float inc = pl;
    #pragma unroll
    for (int off = 1; off < 32; off <<= 1) {
        const float t = __shfl_up_sync(0xffffffffu, inc, off);
        if (lane >= off) inc *= t;
    }
    const float total = __shfl_sync(0xffffffffu, inc, 31);
    float pre = __shfl_up_sync(0xffffffffu, inc, 1);
    if (lane == 0) pre = 1.0f;

    float T = pre, acr = 0.0f, acg = 0.0f, acb = 0.0f;
    #pragma unroll
    for (int q = 0; q < 4; q++) {
        const float w = v[q].w * T;
        acr = fmaf(w, v[q].x, acr);
        acg = fmaf(w, v[q].y, acg);
        acb = fmaf(w, v[q].z, acb);
        T *= ta[q];
    }
    #pragma unroll
    for (int off = 16; off >= 1; off >>= 1) {
        acr += __shfl_xor_sync(0xffffffffu, acr, off);
        acg += __shfl_xor_sync(0xffffffffu, acg, off);
        acb += __shfl_xor_sync(0xffffffffu, acb, off);
    }
    if (lane == 0) {
        out[ray * 3 + 0] = acr + total;
        out[ray * 3 + 1] = acg + total;
        out[ray * 3 + 2] = acb + total;
    }
}

extern "C" void kernel_launch(void* const* d_in, const int* in_sizes, int n_in,
                              void* d_out, int out_size) {
    const float* rays_o  = (const float*)d_in[0];
    const float* rays_d  = (const float*)d_in[1];
    const float* near_   = (const float*)d_in[2];
    const float* far_    = (const float*)d_in[3];
    const float* jitter  = (const float*)d_in[4];
    const float* density = (const float*)d_in[5];
    const float* W1      = (const float*)d_in[6];
    const float* b1      = (const float*)d_in[7];
    const float* W2      = (const float*)d_in[8];
    const float* b2      = (const float*)d_in[9];
    const float* Wsig    = (const float*)d_in[10];
    const float* bsig    = (const float*)d_in[11];
    const float* Wrgb    = (const float*)d_in[12];
    const float* brgb    = (const float*)d_in[13];
    float* out = (float*)d_out;

    const int nrays = in_sizes[2];

    compact_kernel<<<(nrays + 1) / 2, 256>>>(rays_o, rays_d, near_, far_,
                                             jitter, density, nrays);
    mlp_kernel<<<MLP_GRID, MLP_BLK>>>(near_, far_, W1, b1, W2, b2,
                                      Wsig, bsig, Wrgb, brgb);
    composite_kernel<<<(nrays + 7) / 8, 256>>>(out, nrays);
}